// round 1
// baseline (speedup 1.0000x reference)
#include <cuda_runtime.h>
#include <cuda_bf16.h>
#include <math.h>

// ----------------------------------------------------------------------------
// TransformerEncoder baseline (round 1): pure fp32, fused epilogues,
// flash-style attention with off-by-one online softmax.
// B=2, N=2048, F=1024, H=16, DH=64, MLP=4096.  T = B*N = 4096 tokens.
// ----------------------------------------------------------------------------

#define T_TOK   4096
#define FDIM    1024
#define NHEAD   16
#define DHEAD   64
#define MLPDIM  4096
#define SEQ     2048
#define LN_EPS  1e-5f

// Scratch (device globals: allocation-free per harness rules)
__device__ float g_h   [(size_t)T_TOK * FDIM];   // LN1 out, reused for LN2 out
__device__ float g_q   [(size_t)T_TOK * FDIM];
__device__ float g_k   [(size_t)T_TOK * FDIM];
__device__ float g_v   [(size_t)T_TOK * FDIM];
__device__ float g_attn[(size_t)T_TOK * FDIM];
__device__ float g_out [(size_t)T_TOK * FDIM];   // residual-1 output
__device__ float g_m1  [(size_t)T_TOK * MLPDIM];

// ---------------------------------------------------------------- LayerNorm
__global__ void ln_kernel(const float* __restrict__ x,
                          const float* __restrict__ g,
                          const float* __restrict__ b,
                          float* __restrict__ y)
{
    __shared__ float red[16];
    const int row = blockIdx.x;
    const int tid = threadIdx.x;                 // 256 threads, 4 floats each
    const float4 v = reinterpret_cast<const float4*>(x + (size_t)row * FDIM)[tid];

    float s  = v.x + v.y + v.z + v.w;
    float s2 = v.x*v.x + v.y*v.y + v.z*v.z + v.w*v.w;
#pragma unroll
    for (int off = 16; off > 0; off >>= 1) {
        s  += __shfl_xor_sync(0xffffffffu, s,  off);
        s2 += __shfl_xor_sync(0xffffffffu, s2, off);
    }
    const int warp = tid >> 5, lane = tid & 31;
    if (lane == 0) { red[warp] = s; red[8 + warp] = s2; }
    __syncthreads();
    float ts = 0.f, ts2 = 0.f;
#pragma unroll
    for (int i = 0; i < 8; i++) { ts += red[i]; ts2 += red[8 + i]; }

    const float mu  = ts * (1.0f / FDIM);
    const float var = ts2 * (1.0f / FDIM) - mu * mu;
    const float inv = rsqrtf(var + LN_EPS);

    const float4 gg = reinterpret_cast<const float4*>(g)[tid];
    const float4 bb = reinterpret_cast<const float4*>(b)[tid];
    float4 o;
    o.x = (v.x - mu) * inv * gg.x + bb.x;
    o.y = (v.y - mu) * inv * gg.y + bb.y;
    o.z = (v.z - mu) * inv * gg.z + bb.z;
    o.w = (v.w - mu) * inv * gg.w + bb.w;
    reinterpret_cast<float4*>(y + (size_t)row * FDIM)[tid] = o;
}

// ---------------------------------------------------------------- SGEMM
// C[M,N] = A[M,K] @ B[K,N] + bias, optional GELU, optional residual add.
// All of M, N divisible by 128; K divisible by 8. 128x128x8 tile, 256 threads,
// 8x8 per-thread microtile.
enum { EPI_BIAS = 0, EPI_BIAS_GELU = 1, EPI_BIAS_RES = 2, EPI_BIAS_GELU_RES = 3 };

__device__ __forceinline__ float gelu_exact(float x) {
    return 0.5f * x * (1.0f + erff(x * 0.70710678118654752440f));
}

template<int EPI>
__global__ __launch_bounds__(256, 2)
void sgemm_kernel(const float* __restrict__ A, const float* __restrict__ B,
                  const float* __restrict__ bias, const float* __restrict__ res,
                  float* __restrict__ C, int M, int N, int K)
{
    __shared__ float As[8][128];
    __shared__ float Bs[8][128];

    const int bx = blockIdx.x, by = blockIdx.y;
    const int tid = threadIdx.x;

    const int aRow = tid >> 1;            // 0..127
    const int aCol = (tid & 1) * 4;       // 0 or 4
    const int bRow = tid >> 5;            // 0..7
    const int bCol = (tid & 31) * 4;      // 0..124

    const float* Ablk = A + (size_t)(by * 128) * K;
    const float* Bblk = B + bx * 128;

    const int tr = (tid >> 4) * 8;        // 0..120
    const int tc = (tid & 15) * 8;        // 0..120

    float acc[8][8] = {};

    for (int k0 = 0; k0 < K; k0 += 8) {
        const float4 a4 = *reinterpret_cast<const float4*>(Ablk + (size_t)aRow * K + k0 + aCol);
        As[aCol + 0][aRow] = a4.x;
        As[aCol + 1][aRow] = a4.y;
        As[aCol + 2][aRow] = a4.z;
        As[aCol + 3][aRow] = a4.w;
        *reinterpret_cast<float4*>(&Bs[bRow][bCol]) =
            *reinterpret_cast<const float4*>(Bblk + (size_t)(k0 + bRow) * N + bCol);
        __syncthreads();

#pragma unroll
        for (int kk = 0; kk < 8; kk++) {
            float ar[8], br[8];
#pragma unroll
            for (int i = 0; i < 8; i++) ar[i] = As[kk][tr + i];
#pragma unroll
            for (int j = 0; j < 8; j++) br[j] = Bs[kk][tc + j];
#pragma unroll
            for (int i = 0; i < 8; i++)
#pragma unroll
                for (int j = 0; j < 8; j++)
                    acc[i][j] = fmaf(ar[i], br[j], acc[i][j]);
        }
        __syncthreads();
    }

    // Epilogue
    const int colBase = bx * 128 + tc;
    const float4 bias0 = *reinterpret_cast<const float4*>(bias + colBase);
    const float4 bias1 = *reinterpret_cast<const float4*>(bias + colBase + 4);

#pragma unroll
    for (int i = 0; i < 8; i++) {
        const int row = by * 128 + tr + i;
        const size_t coff = (size_t)row * N + colBase;
        float4 r0, r1;
        r0.x = acc[i][0] + bias0.x; r0.y = acc[i][1] + bias0.y;
        r0.z = acc[i][2] + bias0.z; r0.w = acc[i][3] + bias0.w;
        r1.x = acc[i][4] + bias1.x; r1.y = acc[i][5] + bias1.y;
        r1.z = acc[i][6] + bias1.z; r1.w = acc[i][7] + bias1.w;
        if (EPI == EPI_BIAS_GELU || EPI == EPI_BIAS_GELU_RES) {
            r0.x = gelu_exact(r0.x); r0.y = gelu_exact(r0.y);
            r0.z = gelu_exact(r0.z); r0.w = gelu_exact(r0.w);
            r1.x = gelu_exact(r1.x); r1.y = gelu_exact(r1.y);
            r1.z = gelu_exact(r1.z); r1.w = gelu_exact(r1.w);
        }
        if (EPI == EPI_BIAS_RES || EPI == EPI_BIAS_GELU_RES) {
            const float4 e0 = *reinterpret_cast<const float4*>(res + coff);
            const float4 e1 = *reinterpret_cast<const float4*>(res + coff + 4);
            r0.x += e0.x; r0.y += e0.y; r0.z += e0.z; r0.w += e0.w;
            r1.x += e1.x; r1.y += e1.y; r1.z += e1.z; r1.w += e1.w;
        }
        *reinterpret_cast<float4*>(C + coff)     = r0;
        *reinterpret_cast<float4*>(C + coff + 4) = r1;
    }
}

// ---------------------------------------------------------------- Attention
// Flash-style, fp32. Each thread owns one query row (q and o in registers).
// grid = (B*H, SEQ/128), block = 128 threads. Off-by-one softmax:
// denom = sum_j exp(a_j - m) + exp(0 - m); slim[h] folded into final scale.
__global__ __launch_bounds__(128)
void attn_kernel(const float* __restrict__ slim)
{
    __shared__ float4 Ks[512];  // 32 keys x 16 float4 (64 floats)
    __shared__ float4 Vs[512];

    const int bh  = blockIdx.x;
    const int b   = bh >> 4;
    const int h   = bh & 15;
    const int tid = threadIdx.x;
    const int t   = b * SEQ + blockIdx.y * 128 + tid;   // global token of my query row

    const float4* qp = reinterpret_cast<const float4*>(g_q + (size_t)t * FDIM + h * DHEAD);
    float4 q[16];
#pragma unroll
    for (int i = 0; i < 16; i++) {
        float4 u = qp[i];
        q[i] = make_float4(u.x * 0.125f, u.y * 0.125f, u.z * 0.125f, u.w * 0.125f);
    }
    float4 o[16];
#pragma unroll
    for (int i = 0; i < 16; i++) o[i] = make_float4(0.f, 0.f, 0.f, 0.f);

    float mrun = -1e30f, srun = 0.f;

#pragma unroll 1
    for (int j0 = 0; j0 < SEQ; j0 += 32) {
        __syncthreads();
#pragma unroll
        for (int i = 0; i < 4; i++) {
            const int f  = tid + i * 128;                  // 0..511
            const int kr = f >> 4, c = f & 15;
            const size_t src = (size_t)(b * SEQ + j0 + kr) * FDIM + h * DHEAD;
            Ks[f] = reinterpret_cast<const float4*>(g_k + src)[c];
            Vs[f] = reinterpret_cast<const float4*>(g_v + src)[c];
        }
        __syncthreads();

#pragma unroll 1
        for (int jj = 0; jj < 32; jj++) {
            const float4* kr = &Ks[jj * 16];
            float s0 = 0.f, s1 = 0.f, s2 = 0.f, s3 = 0.f;
#pragma unroll
            for (int d = 0; d < 16; d += 4) {
                const float4 k0 = kr[d], k1 = kr[d + 1], k2 = kr[d + 2], k3 = kr[d + 3];
                s0 += q[d].x   * k0.x + q[d].y   * k0.y + q[d].z   * k0.z + q[d].w   * k0.w;
                s1 += q[d+1].x * k1.x + q[d+1].y * k1.y + q[d+1].z * k1.z + q[d+1].w * k1.w;
                s2 += q[d+2].x * k2.x + q[d+2].y * k2.y + q[d+2].z * k2.z + q[d+2].w * k2.w;
                s3 += q[d+3].x * k3.x + q[d+3].y * k3.y + q[d+3].z * k3.z + q[d+3].w * k3.w;
            }
            const float s = (s0 + s1) + (s2 + s3);

            const float mnew  = fmaxf(mrun, s);
            const float corr  = __expf(mrun - mnew);
            const float p     = __expf(s - mnew);
            srun = srun * corr + p;
            mrun = mnew;

            const float4* vr = &Vs[jj * 16];
#pragma unroll
            for (int d = 0; d < 16; d++) {
                const float4 vv = vr[d];
                o[d].x = fmaf(o[d].x, corr, p * vv.x);
                o[d].y = fmaf(o[d].y, corr, p * vv.y);
                o[d].z = fmaf(o[d].z, corr, p * vv.z);
                o[d].w = fmaf(o[d].w, corr, p * vv.w);
            }
        }
    }

    // off-by-one denominator: + exp(0 - mrun)
    const float denom = srun + __expf(-mrun);
    const float w = slim[h] / denom;

    float4* op = reinterpret_cast<float4*>(g_attn + (size_t)t * FDIM + h * DHEAD);
#pragma unroll
    for (int d = 0; d < 16; d++)
        op[d] = make_float4(o[d].x * w, o[d].y * w, o[d].z * w, o[d].w * w);
}

// ---------------------------------------------------------------- launch
static float* sym_addr(const void* symbol)
{
    void* p = nullptr;
    cudaGetSymbolAddress(&p, symbol);
    return reinterpret_cast<float*>(p);
}

extern "C" void kernel_launch(void* const* d_in, const int* in_sizes, int n_in,
                              void* d_out, int out_size)
{
    const float* x     = (const float*)d_in[0];
    const float* ln1_g = (const float*)d_in[1];
    const float* ln1_b = (const float*)d_in[2];
    const float* Wq    = (const float*)d_in[3];
    const float* bq    = (const float*)d_in[4];
    const float* Wk    = (const float*)d_in[5];
    const float* bk    = (const float*)d_in[6];
    const float* Wv    = (const float*)d_in[7];
    const float* bv    = (const float*)d_in[8];
    const float* Wo    = (const float*)d_in[9];
    const float* bo    = (const float*)d_in[10];
    const float* slim  = (const float*)d_in[11];
    const float* ln2_g = (const float*)d_in[12];
    const float* ln2_b = (const float*)d_in[13];
    const float* W1    = (const float*)d_in[14];
    const float* b1    = (const float*)d_in[15];
    const float* W2    = (const float*)d_in[16];
    const float* b2    = (const float*)d_in[17];
    float* out = (float*)d_out;

    float* h_p    = sym_addr(g_h);
    float* q_p    = sym_addr(g_q);
    float* k_p    = sym_addr(g_k);
    float* v_p    = sym_addr(g_v);
    float* attn_p = sym_addr(g_attn);
    float* out_p  = sym_addr(g_out);
    float* m1_p   = sym_addr(g_m1);

    const dim3 blk256(256);
    const dim3 gridF(FDIM / 128, T_TOK / 128);     // N=1024 GEMMs
    const dim3 gridM(MLPDIM / 128, T_TOK / 128);   // N=4096 GEMM (W1)

    // 1) LN1
    ln_kernel<<<T_TOK, blk256>>>(x, ln1_g, ln1_b, h_p);

    // 2) QKV projections
    sgemm_kernel<EPI_BIAS><<<gridF, blk256>>>(h_p, Wq, bq, nullptr, q_p, T_TOK, FDIM, FDIM);
    sgemm_kernel<EPI_BIAS><<<gridF, blk256>>>(h_p, Wk, bk, nullptr, k_p, T_TOK, FDIM, FDIM);
    sgemm_kernel<EPI_BIAS><<<gridF, blk256>>>(h_p, Wv, bv, nullptr, v_p, T_TOK, FDIM, FDIM);

    // 3) Attention (flash, off-by-one softmax, slimming)
    attn_kernel<<<dim3(2 * NHEAD, SEQ / 128), dim3(128)>>>(slim);

    // 4) Output projection + residual 1
    sgemm_kernel<EPI_BIAS_RES><<<gridF, blk256>>>(attn_p, Wo, bo, x, out_p, T_TOK, FDIM, FDIM);

    // 5) LN2
    ln_kernel<<<T_TOK, blk256>>>(out_p, ln2_g, ln2_b, h_p);

    // 6) MLP
    sgemm_kernel<EPI_BIAS_GELU><<<gridM, blk256>>>(h_p, W1, b1, nullptr, m1_p, T_TOK, MLPDIM, FDIM);
    sgemm_kernel<EPI_BIAS_GELU_RES><<<gridF, blk256>>>(m1_p, W2, b2, out_p, out, T_TOK, FDIM, MLPDIM);
}